// round 5
// baseline (speedup 1.0000x reference)
#include <cuda_runtime.h>
#include <cuda_bf16.h>
#include <cstdint>

// NT-Xent loss, fused. N=4096 rows per view, 2N=8192 total, D=128, T=0.5.
// loss_i = -2*p_i + log(S_i - exp(2*d_i) + exp(2*p_i)),  S_i = sum_j exp(2*sim[i,j])

#define NROWS 8192
#define HALF_N 4096
#define DIM 128

__device__ __align__(16) __nv_bfloat16 g_R[NROWS * DIM];
__device__ float g_S[NROWS];
__device__ float g_pos[NROWS];
__device__ float g_diag[NROWS];

// ---------------- kernel 1: L2 normalize rows, write bf16 ----------------
__global__ void k_normalize(const float* __restrict__ zi, const float* __restrict__ zj) {
    int warp = (blockIdx.x * blockDim.x + threadIdx.x) >> 5;
    int lane = threadIdx.x & 31;
    if (warp >= NROWS) return;
    const float* src = (warp < HALF_N) ? (zi + (size_t)warp * DIM)
                                       : (zj + (size_t)(warp - HALF_N) * DIM);
    float4 v = reinterpret_cast<const float4*>(src)[lane];
    float ss = v.x * v.x + v.y * v.y + v.z * v.z + v.w * v.w;
    #pragma unroll
    for (int o = 16; o; o >>= 1) ss += __shfl_xor_sync(0xffffffffu, ss, o);
    float n = sqrtf(ss);
    float inv = 1.0f / fmaxf(n, 1e-12f);
    __nv_bfloat162 p0 = __nv_bfloat162(__float2bfloat16(v.x * inv), __float2bfloat16(v.y * inv));
    __nv_bfloat162 p1 = __nv_bfloat162(__float2bfloat16(v.z * inv), __float2bfloat16(v.w * inv));
    uint2 packed;
    packed.x = *reinterpret_cast<uint32_t*>(&p0);
    packed.y = *reinterpret_cast<uint32_t*>(&p1);
    reinterpret_cast<uint2*>(g_R + (size_t)warp * DIM)[lane] = packed;
}

// ------------- kernel 2: positives, diagonal, zero S --------------------
__global__ void k_pairs() {
    int warp = (blockIdx.x * blockDim.x + threadIdx.x) >> 5;
    int lane = threadIdx.x & 31;
    if (warp >= NROWS) return;
    int j = warp ^ HALF_N;  // (i + N) mod 2N for power-of-two N
    uint2 va = reinterpret_cast<const uint2*>(g_R + (size_t)warp * DIM)[lane];
    uint2 vb = reinterpret_cast<const uint2*>(g_R + (size_t)j * DIM)[lane];
    __nv_bfloat162 a0 = *reinterpret_cast<__nv_bfloat162*>(&va.x);
    __nv_bfloat162 a1 = *reinterpret_cast<__nv_bfloat162*>(&va.y);
    __nv_bfloat162 b0 = *reinterpret_cast<__nv_bfloat162*>(&vb.x);
    __nv_bfloat162 b1 = *reinterpret_cast<__nv_bfloat162*>(&vb.y);
    float ax = __bfloat162float(a0.x), ay = __bfloat162float(a0.y);
    float az = __bfloat162float(a1.x), aw = __bfloat162float(a1.y);
    float bx = __bfloat162float(b0.x), by = __bfloat162float(b0.y);
    float bz = __bfloat162float(b1.x), bw = __bfloat162float(b1.y);
    float p = ax * bx + ay * by + az * bz + aw * bw;
    float d = ax * ax + ay * ay + az * az + aw * aw;
    #pragma unroll
    for (int o = 16; o; o >>= 1) {
        p += __shfl_xor_sync(0xffffffffu, p, o);
        d += __shfl_xor_sync(0xffffffffu, d, o);
    }
    if (lane == 0) {
        g_pos[warp] = p;
        g_diag[warp] = d;
        g_S[warp] = 0.0f;
    }
}

// ------------- kernel 3: tiled bf16 MMA + fused exp row-sum -------------
#define BM 128
#define BN 128
#define BK 64
#define SSTRIDE (BK + 8)  // bf16 elems; 144B row stride, 16B aligned

__device__ __forceinline__ void ldmatrix_x4(uint32_t* r, const __nv_bfloat16* p) {
    uint32_t addr = (uint32_t)__cvta_generic_to_shared(p);
    asm volatile("ldmatrix.sync.aligned.m8n8.x4.shared.b16 {%0,%1,%2,%3}, [%4];"
                 : "=r"(r[0]), "=r"(r[1]), "=r"(r[2]), "=r"(r[3]) : "r"(addr));
}
__device__ __forceinline__ void ldmatrix_x2(uint32_t* r, const __nv_bfloat16* p) {
    uint32_t addr = (uint32_t)__cvta_generic_to_shared(p);
    asm volatile("ldmatrix.sync.aligned.m8n8.x2.shared.b16 {%0,%1}, [%2];"
                 : "=r"(r[0]), "=r"(r[1]) : "r"(addr));
}
__device__ __forceinline__ void mma_bf16(float* c, const uint32_t* a, const uint32_t* b) {
    asm volatile(
        "mma.sync.aligned.m16n8k16.row.col.f32.bf16.bf16.f32 "
        "{%0,%1,%2,%3}, {%4,%5,%6,%7}, {%8,%9}, {%0,%1,%2,%3};"
        : "+f"(c[0]), "+f"(c[1]), "+f"(c[2]), "+f"(c[3])
        : "r"(a[0]), "r"(a[1]), "r"(a[2]), "r"(a[3]), "r"(b[0]), "r"(b[1]));
}

__global__ void __launch_bounds__(256) k_simexp() {
    __shared__ __nv_bfloat16 As[BM * SSTRIDE];
    __shared__ __nv_bfloat16 Bs[BN * SSTRIDE];
    __shared__ float rowsum[BM];

    int tid = threadIdx.x;
    int wid = tid >> 5, lane = tid & 31;
    int wm = wid >> 2, wn = wid & 3;  // 2x4 warp grid; warp tile 64x32
    int bi = blockIdx.x, bj = blockIdx.y;

    float c[4][4][4];
    #pragma unroll
    for (int mf = 0; mf < 4; mf++)
        #pragma unroll
        for (int nf = 0; nf < 4; nf++)
            #pragma unroll
            for (int e = 0; e < 4; e++) c[mf][nf][e] = 0.0f;

    if (tid < BM) rowsum[tid] = 0.0f;

    #pragma unroll
    for (int k0 = 0; k0 < DIM; k0 += BK) {
        const uint4* gA = reinterpret_cast<const uint4*>(g_R + (size_t)(bi * BM) * DIM + k0);
        const uint4* gB = reinterpret_cast<const uint4*>(g_R + (size_t)(bj * BM) * DIM + k0);
        // 128 rows x 8 uint4 per tile; 256 threads x 4 iters
        #pragma unroll
        for (int it = 0; it < 4; it++) {
            int idx = tid + 256 * it;
            int r = idx >> 3, c8 = idx & 7;
            *reinterpret_cast<uint4*>(&As[r * SSTRIDE + c8 * 8]) = gA[r * 16 + c8];
            *reinterpret_cast<uint4*>(&Bs[r * SSTRIDE + c8 * 8]) = gB[r * 16 + c8];
        }
        __syncthreads();

        #pragma unroll
        for (int kk = 0; kk < BK; kk += 16) {
            uint32_t a[4][4];
            #pragma unroll
            for (int mf = 0; mf < 4; mf++) {
                const __nv_bfloat16* p =
                    &As[(wm * 64 + mf * 16 + (lane & 15)) * SSTRIDE + kk + (lane >> 4) * 8];
                ldmatrix_x4(a[mf], p);
            }
            uint32_t b[4][2];
            #pragma unroll
            for (int nf = 0; nf < 4; nf++) {
                const __nv_bfloat16* p =
                    &Bs[(wn * 32 + nf * 8 + (lane & 7)) * SSTRIDE + kk + ((lane & 15) >> 3) * 8];
                ldmatrix_x2(b[nf], p);
            }
            #pragma unroll
            for (int mf = 0; mf < 4; mf++)
                #pragma unroll
                for (int nf = 0; nf < 4; nf++)
                    mma_bf16(c[mf][nf], a[mf], b[nf]);
        }
        __syncthreads();
    }

    // epilogue: exp(2*sim), reduce per row
    int g = lane >> 2;
    #pragma unroll
    for (int mf = 0; mf < 4; mf++) {
        float rs0 = 0.0f, rs1 = 0.0f;
        #pragma unroll
        for (int nf = 0; nf < 4; nf++) {
            rs0 += __expf(2.0f * c[mf][nf][0]) + __expf(2.0f * c[mf][nf][1]);
            rs1 += __expf(2.0f * c[mf][nf][2]) + __expf(2.0f * c[mf][nf][3]);
        }
        #pragma unroll
        for (int o = 1; o < 4; o <<= 1) {
            rs0 += __shfl_xor_sync(0xffffffffu, rs0, o);
            rs1 += __shfl_xor_sync(0xffffffffu, rs1, o);
        }
        if ((lane & 3) == 0) {
            atomicAdd(&rowsum[wm * 64 + mf * 16 + g], rs0);
            atomicAdd(&rowsum[wm * 64 + mf * 16 + g + 8], rs1);
        }
    }
    __syncthreads();
    if (tid < BM) atomicAdd(&g_S[bi * BM + tid], rowsum[tid]);
}

// ------------- kernel 4: finalize -----------------------------------------
__global__ void k_final(float* __restrict__ out) {
    __shared__ float red[256];
    int tid = threadIdx.x;
    float acc = 0.0f;
    for (int i = tid; i < NROWS; i += 256) {
        float p = g_pos[i];
        float d = g_diag[i];
        float S = g_S[i];
        float denom = S - __expf(2.0f * d) + __expf(2.0f * p);
        acc += -2.0f * p + logf(denom);
    }
    red[tid] = acc;
    __syncthreads();
    #pragma unroll
    for (int s = 128; s > 0; s >>= 1) {
        if (tid < s) red[tid] += red[tid + s];
        __syncthreads();
    }
    if (tid == 0) out[0] = red[0] / (float)NROWS;
}

extern "C" void kernel_launch(void* const* d_in, const int* in_sizes, int n_in,
                              void* d_out, int out_size) {
    const float* zi = (const float*)d_in[0];
    const float* zj = (const float*)d_in[1];
    float* out = (float*)d_out;
    (void)in_sizes; (void)n_in; (void)out_size;

    k_normalize<<<NROWS / 8, 256>>>(zi, zj);       // 8 warps/block
    k_pairs<<<NROWS / 8, 256>>>();
    dim3 grid(NROWS / BM, NROWS / BN);
    k_simexp<<<grid, 256>>>();
    k_final<<<1, 256>>>(out);
}

// round 6
// speedup vs baseline: 1.5276x; 1.5276x over previous
#include <cuda_runtime.h>
#include <cuda_bf16.h>
#include <cstdint>

// NT-Xent loss, fused + symmetric-triangle GEMM.
// loss_i = -2*p_i + log(S_i - exp(2*d_i) + exp(2*p_i)),  S_i = sum_j exp(2*sim[i,j])
// sim = R R^T is symmetric: compute lower-triangle tiles only; each off-diagonal
// tile contributes row-sums (block bi) AND column-sums (block bj) from the same
// exp values.

#define NROWS 8192
#define HALF_N 4096
#define DIM 128

__device__ __align__(16) __nv_bfloat16 g_R[NROWS * DIM];
__device__ float g_S[NROWS];
__device__ float g_pos[NROWS];
__device__ float g_diag[NROWS];

// ---------------- kernel 1: L2 normalize rows, write bf16 ----------------
__global__ void k_normalize(const float* __restrict__ zi, const float* __restrict__ zj) {
    int warp = (blockIdx.x * blockDim.x + threadIdx.x) >> 5;
    int lane = threadIdx.x & 31;
    if (warp >= NROWS) return;
    const float* src = (warp < HALF_N) ? (zi + (size_t)warp * DIM)
                                       : (zj + (size_t)(warp - HALF_N) * DIM);
    float4 v = reinterpret_cast<const float4*>(src)[lane];
    float ss = v.x * v.x + v.y * v.y + v.z * v.z + v.w * v.w;
    #pragma unroll
    for (int o = 16; o; o >>= 1) ss += __shfl_xor_sync(0xffffffffu, ss, o);
    float n = sqrtf(ss);
    float inv = 1.0f / fmaxf(n, 1e-12f);
    __nv_bfloat162 p0 = __nv_bfloat162(__float2bfloat16(v.x * inv), __float2bfloat16(v.y * inv));
    __nv_bfloat162 p1 = __nv_bfloat162(__float2bfloat16(v.z * inv), __float2bfloat16(v.w * inv));
    uint2 packed;
    packed.x = *reinterpret_cast<uint32_t*>(&p0);
    packed.y = *reinterpret_cast<uint32_t*>(&p1);
    reinterpret_cast<uint2*>(g_R + (size_t)warp * DIM)[lane] = packed;
}

// ------------- kernel 2: positives, diagonal, zero S, zero out ----------
__global__ void k_pairs(float* __restrict__ out) {
    int warp = (blockIdx.x * blockDim.x + threadIdx.x) >> 5;
    int lane = threadIdx.x & 31;
    if (blockIdx.x == 0 && threadIdx.x == 0) out[0] = 0.0f;
    if (warp >= NROWS) return;
    int j = warp ^ HALF_N;  // (i + N) mod 2N for power-of-two N
    uint2 va = reinterpret_cast<const uint2*>(g_R + (size_t)warp * DIM)[lane];
    uint2 vb = reinterpret_cast<const uint2*>(g_R + (size_t)j * DIM)[lane];
    __nv_bfloat162 a0 = *reinterpret_cast<__nv_bfloat162*>(&va.x);
    __nv_bfloat162 a1 = *reinterpret_cast<__nv_bfloat162*>(&va.y);
    __nv_bfloat162 b0 = *reinterpret_cast<__nv_bfloat162*>(&vb.x);
    __nv_bfloat162 b1 = *reinterpret_cast<__nv_bfloat162*>(&vb.y);
    float ax = __bfloat162float(a0.x), ay = __bfloat162float(a0.y);
    float az = __bfloat162float(a1.x), aw = __bfloat162float(a1.y);
    float bx = __bfloat162float(b0.x), by = __bfloat162float(b0.y);
    float bz = __bfloat162float(b1.x), bw = __bfloat162float(b1.y);
    float p = ax * bx + ay * by + az * bz + aw * bw;
    float d = ax * ax + ay * ay + az * az + aw * aw;
    #pragma unroll
    for (int o = 16; o; o >>= 1) {
        p += __shfl_xor_sync(0xffffffffu, p, o);
        d += __shfl_xor_sync(0xffffffffu, d, o);
    }
    if (lane == 0) {
        g_pos[warp] = p;
        g_diag[warp] = d;
        g_S[warp] = 0.0f;
    }
}

// ------------- kernel 3: lower-triangle bf16 MMA + fused exp sums -------
#define BM 128
#define BN 128
#define BK 64
#define SSTRIDE (BK + 8)  // bf16 elems; 144B row stride, 16B aligned

__device__ __forceinline__ void ldmatrix_x4(uint32_t* r, const __nv_bfloat16* p) {
    uint32_t addr = (uint32_t)__cvta_generic_to_shared(p);
    asm volatile("ldmatrix.sync.aligned.m8n8.x4.shared.b16 {%0,%1,%2,%3}, [%4];"
                 : "=r"(r[0]), "=r"(r[1]), "=r"(r[2]), "=r"(r[3]) : "r"(addr));
}
__device__ __forceinline__ void ldmatrix_x2(uint32_t* r, const __nv_bfloat16* p) {
    uint32_t addr = (uint32_t)__cvta_generic_to_shared(p);
    asm volatile("ldmatrix.sync.aligned.m8n8.x2.shared.b16 {%0,%1}, [%2];"
                 : "=r"(r[0]), "=r"(r[1]) : "r"(addr));
}
__device__ __forceinline__ void mma_bf16(float* c, const uint32_t* a, const uint32_t* b) {
    asm volatile(
        "mma.sync.aligned.m16n8k16.row.col.f32.bf16.bf16.f32 "
        "{%0,%1,%2,%3}, {%4,%5,%6,%7}, {%8,%9}, {%0,%1,%2,%3};"
        : "+f"(c[0]), "+f"(c[1]), "+f"(c[2]), "+f"(c[3])
        : "r"(a[0]), "r"(a[1]), "r"(a[2]), "r"(a[3]), "r"(b[0]), "r"(b[1]));
}

__global__ void __launch_bounds__(256) k_simexp() {
    int bi = blockIdx.x, bj = blockIdx.y;
    if (bj > bi) return;  // lower triangle only
    bool offdiag = (bi != bj);

    __shared__ __nv_bfloat16 As[BM * SSTRIDE];
    __shared__ __nv_bfloat16 Bs[BN * SSTRIDE];
    __shared__ float rowsum[BM];
    __shared__ float colsum[BN];

    int tid = threadIdx.x;
    int wid = tid >> 5, lane = tid & 31;
    int wm = wid >> 2, wn = wid & 3;  // 2x4 warp grid; warp tile 64x32

    float c[4][4][4];
    #pragma unroll
    for (int mf = 0; mf < 4; mf++)
        #pragma unroll
        for (int nf = 0; nf < 4; nf++)
            #pragma unroll
            for (int e = 0; e < 4; e++) c[mf][nf][e] = 0.0f;

    if (tid < BM) { rowsum[tid] = 0.0f; colsum[tid] = 0.0f; }

    #pragma unroll
    for (int k0 = 0; k0 < DIM; k0 += BK) {
        const uint4* gA = reinterpret_cast<const uint4*>(g_R + (size_t)(bi * BM) * DIM + k0);
        const uint4* gB = reinterpret_cast<const uint4*>(g_R + (size_t)(bj * BM) * DIM + k0);
        #pragma unroll
        for (int it = 0; it < 4; it++) {
            int idx = tid + 256 * it;
            int r = idx >> 3, c8 = idx & 7;
            *reinterpret_cast<uint4*>(&As[r * SSTRIDE + c8 * 8]) = gA[r * 16 + c8];
            *reinterpret_cast<uint4*>(&Bs[r * SSTRIDE + c8 * 8]) = gB[r * 16 + c8];
        }
        __syncthreads();

        #pragma unroll
        for (int kk = 0; kk < BK; kk += 16) {
            uint32_t a[4][4];
            #pragma unroll
            for (int mf = 0; mf < 4; mf++) {
                const __nv_bfloat16* p =
                    &As[(wm * 64 + mf * 16 + (lane & 15)) * SSTRIDE + kk + (lane >> 4) * 8];
                ldmatrix_x4(a[mf], p);
            }
            uint32_t b[4][2];
            #pragma unroll
            for (int nf = 0; nf < 4; nf++) {
                const __nv_bfloat16* p =
                    &Bs[(wn * 32 + nf * 8 + (lane & 7)) * SSTRIDE + kk + ((lane & 15) >> 3) * 8];
                ldmatrix_x2(b[nf], p);
            }
            #pragma unroll
            for (int mf = 0; mf < 4; mf++)
                #pragma unroll
                for (int nf = 0; nf < 4; nf++)
                    mma_bf16(c[mf][nf], a[mf], b[nf]);
        }
        __syncthreads();
    }

    // epilogue: exp(2*sim); row-sums always, column-sums when off-diagonal.
    // fragment (mf,nf,e): row = wm*64+mf*16+(lane>>2)+(e>=2?8:0),
    //                     col = wn*32+nf*8+(lane&3)*2+(e&1)
    int g = lane >> 2;
    float csA[4], csB[4];  // per nf: cols (lane&3)*2 and +1, acc over mf & rows
    #pragma unroll
    for (int nf = 0; nf < 4; nf++) { csA[nf] = 0.0f; csB[nf] = 0.0f; }

    #pragma unroll
    for (int mf = 0; mf < 4; mf++) {
        float rs0 = 0.0f, rs1 = 0.0f;
        #pragma unroll
        for (int nf = 0; nf < 4; nf++) {
            float e0 = __expf(2.0f * c[mf][nf][0]);
            float e1 = __expf(2.0f * c[mf][nf][1]);
            float e2 = __expf(2.0f * c[mf][nf][2]);
            float e3 = __expf(2.0f * c[mf][nf][3]);
            rs0 += e0 + e1;
            rs1 += e2 + e3;
            csA[nf] += e0 + e2;
            csB[nf] += e1 + e3;
        }
        #pragma unroll
        for (int o = 1; o < 4; o <<= 1) {
            rs0 += __shfl_xor_sync(0xffffffffu, rs0, o);
            rs1 += __shfl_xor_sync(0xffffffffu, rs1, o);
        }
        if ((lane & 3) == 0) {
            atomicAdd(&rowsum[wm * 64 + mf * 16 + g], rs0);
            atomicAdd(&rowsum[wm * 64 + mf * 16 + g + 8], rs1);
        }
    }

    if (offdiag) {
        #pragma unroll
        for (int nf = 0; nf < 4; nf++) {
            float a = csA[nf], b = csB[nf];
            #pragma unroll
            for (int o = 4; o < 32; o <<= 1) {
                a += __shfl_xor_sync(0xffffffffu, a, o);
                b += __shfl_xor_sync(0xffffffffu, b, o);
            }
            if (lane < 4) {
                atomicAdd(&colsum[wn * 32 + nf * 8 + lane * 2], a);
                atomicAdd(&colsum[wn * 32 + nf * 8 + lane * 2 + 1], b);
            }
        }
    }
    __syncthreads();
    if (tid < BM) atomicAdd(&g_S[bi * BM + tid], rowsum[tid]);
    if (offdiag && tid < BN) atomicAdd(&g_S[bj * BN + tid], colsum[tid]);
}

// ------------- kernel 4: finalize (parallel) ------------------------------
__global__ void k_final(float* __restrict__ out) {
    __shared__ float red[256];
    int tid = threadIdx.x;
    int i = blockIdx.x * 256 + tid;  // 32 blocks x 256 = 8192 rows
    float p = g_pos[i];
    float d = g_diag[i];
    float S = g_S[i];
    float denom = S - __expf(2.0f * d) + __expf(2.0f * p);
    red[tid] = -2.0f * p + logf(denom);
    __syncthreads();
    #pragma unroll
    for (int s = 128; s > 0; s >>= 1) {
        if (tid < s) red[tid] += red[tid + s];
        __syncthreads();
    }
    if (tid == 0) atomicAdd(out, red[0] / (float)NROWS);
}

extern "C" void kernel_launch(void* const* d_in, const int* in_sizes, int n_in,
                              void* d_out, int out_size) {
    const float* zi = (const float*)d_in[0];
    const float* zj = (const float*)d_in[1];
    float* out = (float*)d_out;
    (void)in_sizes; (void)n_in; (void)out_size;

    k_normalize<<<NROWS / 8, 256>>>(zi, zj);  // 8 warps/block
    k_pairs<<<NROWS / 8, 256>>>(out);         // also zeroes out[0], g_S
    dim3 grid(NROWS / BM, NROWS / BN);
    k_simexp<<<grid, 256>>>();                // lower triangle active
    k_final<<<32, 256>>>(out);
}

// round 9
// speedup vs baseline: 1.6245x; 1.0634x over previous
#include <cuda_runtime.h>
#include <cuda_bf16.h>
#include <cuda_fp8.h>
#include <cstdint>

// NT-Xent loss. loss_i = -2*p_i + log(S_i - exp(2*d_i) + exp(2*p_i)),
// S_i = sum_j exp(2*sim[i,j]), sim = R R^T (symmetric -> lower triangle only).
// Round 8: legacy-path FP8 (e4m3, m16n8k32) GEMM; tcgen05 is unavailable
// (harness PTX target is sm_103 without the 'a' feature set).
// R rows stored twice: bf16 (exact pos/diag) and e4m3 scaled by 16 (GEMM).

#define NROWS 8192
#define HALF_N 4096
#define DIM 128

__device__ __align__(16) __nv_bfloat16 g_R[NROWS * DIM];
__device__ __align__(16) uint8_t g_R8[NROWS * DIM];   // e4m3, rows scaled by 16
__device__ float g_S[NROWS];
__device__ float g_pos[NROWS];
__device__ float g_diag[NROWS];

// ---------------- kernel 1: L2 normalize rows, write bf16 + fp8 ----------
__global__ void k_normalize(const float* __restrict__ zi, const float* __restrict__ zj) {
    int warp = (blockIdx.x * blockDim.x + threadIdx.x) >> 5;
    int lane = threadIdx.x & 31;
    if (warp >= NROWS) return;
    const float* src = (warp < HALF_N) ? (zi + (size_t)warp * DIM)
                                       : (zj + (size_t)(warp - HALF_N) * DIM);
    float4 v = reinterpret_cast<const float4*>(src)[lane];
    float ss = v.x * v.x + v.y * v.y + v.z * v.z + v.w * v.w;
    #pragma unroll
    for (int o = 16; o; o >>= 1) ss += __shfl_xor_sync(0xffffffffu, ss, o);
    float inv = 1.0f / fmaxf(sqrtf(ss), 1e-12f);
    float x = v.x * inv, y = v.y * inv, z = v.z * inv, w = v.w * inv;

    __nv_bfloat162 p0 = __nv_bfloat162(__float2bfloat16(x), __float2bfloat16(y));
    __nv_bfloat162 p1 = __nv_bfloat162(__float2bfloat16(z), __float2bfloat16(w));
    uint2 packed;
    packed.x = *reinterpret_cast<uint32_t*>(&p0);
    packed.y = *reinterpret_cast<uint32_t*>(&p1);
    reinterpret_cast<uint2*>(g_R + (size_t)warp * DIM)[lane] = packed;

    // fp8: scale by 16 (power of 2; |elem|<=1 -> <=16 < 448 max e4m3)
    uint32_t q = (uint32_t)__nv_cvt_float_to_fp8(x * 16.0f, __NV_SATFINITE, __NV_E4M3)
               | ((uint32_t)__nv_cvt_float_to_fp8(y * 16.0f, __NV_SATFINITE, __NV_E4M3) << 8)
               | ((uint32_t)__nv_cvt_float_to_fp8(z * 16.0f, __NV_SATFINITE, __NV_E4M3) << 16)
               | ((uint32_t)__nv_cvt_float_to_fp8(w * 16.0f, __NV_SATFINITE, __NV_E4M3) << 24);
    reinterpret_cast<uint32_t*>(g_R8 + (size_t)warp * DIM)[lane] = q;
}

// ------------- kernel 2: positives, diagonal, zero S, zero out ----------
__global__ void k_pairs(float* __restrict__ out) {
    int warp = (blockIdx.x * blockDim.x + threadIdx.x) >> 5;
    int lane = threadIdx.x & 31;
    if (blockIdx.x == 0 && threadIdx.x == 0) out[0] = 0.0f;
    if (warp >= NROWS) return;
    int j = warp ^ HALF_N;
    uint2 va = reinterpret_cast<const uint2*>(g_R + (size_t)warp * DIM)[lane];
    uint2 vb = reinterpret_cast<const uint2*>(g_R + (size_t)j * DIM)[lane];
    __nv_bfloat162 a0 = *reinterpret_cast<__nv_bfloat162*>(&va.x);
    __nv_bfloat162 a1 = *reinterpret_cast<__nv_bfloat162*>(&va.y);
    __nv_bfloat162 b0 = *reinterpret_cast<__nv_bfloat162*>(&vb.x);
    __nv_bfloat162 b1 = *reinterpret_cast<__nv_bfloat162*>(&vb.y);
    float ax = __bfloat162float(a0.x), ay = __bfloat162float(a0.y);
    float az = __bfloat162float(a1.x), aw = __bfloat162float(a1.y);
    float bx = __bfloat162float(b0.x), by = __bfloat162float(b0.y);
    float bz = __bfloat162float(b1.x), bw = __bfloat162float(b1.y);
    float p = ax * bx + ay * by + az * bz + aw * bw;
    float d = ax * ax + ay * ay + az * az + aw * aw;
    #pragma unroll
    for (int o = 16; o; o >>= 1) {
        p += __shfl_xor_sync(0xffffffffu, p, o);
        d += __shfl_xor_sync(0xffffffffu, d, o);
    }
    if (lane == 0) {
        g_pos[warp] = p;
        g_diag[warp] = d;
        g_S[warp] = 0.0f;
    }
}

// ------------- kernel 3: lower-triangle FP8 MMA + fused exp sums --------
// Tile 128x128, K=128 (one shot). Smem: 144B row stride (128B data + 16 pad)
// -> LDS.32 fragment fetches hit banks (4g+t) mod 32: conflict-free.
#define SROW 144

__device__ __forceinline__ void mma_e4m3(float* c, const uint32_t* a, const uint32_t* b) {
    asm volatile(
        "mma.sync.aligned.m16n8k32.row.col.f32.e4m3.e4m3.f32 "
        "{%0,%1,%2,%3}, {%4,%5,%6,%7}, {%8,%9}, {%0,%1,%2,%3};"
        : "+f"(c[0]), "+f"(c[1]), "+f"(c[2]), "+f"(c[3])
        : "r"(a[0]), "r"(a[1]), "r"(a[2]), "r"(a[3]), "r"(b[0]), "r"(b[1]));
}

__global__ void __launch_bounds__(256) k_simexp() {
    __shared__ uint8_t As[128 * SROW];
    __shared__ uint8_t Bs[128 * SROW];
    __shared__ float rowsum[128];
    __shared__ float colsum[128];

    int tid = threadIdx.x;
    int wid = tid >> 5, lane = tid & 31;
    int wm = wid >> 2, wn = wid & 3;      // 2x4 warp grid; warp tile 64x32
    int g = lane >> 2, tq = lane & 3;     // group / thread-in-group

    // linear block -> lower triangle (bi, bj), bj <= bi
    int t = blockIdx.x;
    int bi = (int)((sqrtf(8.0f * (float)t + 1.0f) - 1.0f) * 0.5f);
    while ((bi + 1) * (bi + 2) / 2 <= t) bi++;
    while (bi * (bi + 1) / 2 > t) bi--;
    int bj = t - bi * (bi + 1) / 2;
    bool offdiag = (bi != bj);

    float c[4][4][4];
    #pragma unroll
    for (int mf = 0; mf < 4; mf++)
        #pragma unroll
        for (int nf = 0; nf < 4; nf++)
            #pragma unroll
            for (int e = 0; e < 4; e++) c[mf][nf][e] = 0.0f;

    if (tid < 128) { rowsum[tid] = 0.0f; colsum[tid] = 0.0f; }

    // ---- load tiles: 128 rows x 128 B each = 1024 uint4 per tile ----
    {
        const uint4* gA = reinterpret_cast<const uint4*>(g_R8 + (size_t)(bi * 128) * DIM);
        const uint4* gB = reinterpret_cast<const uint4*>(g_R8 + (size_t)(bj * 128) * DIM);
        #pragma unroll
        for (int it = 0; it < 4; it++) {
            int idx = tid + 256 * it;
            int r = idx >> 3, c8 = idx & 7;
            *reinterpret_cast<uint4*>(&As[r * SROW + c8 * 16]) = gA[idx];
            *reinterpret_cast<uint4*>(&Bs[r * SROW + c8 * 16]) = gB[idx];
        }
    }
    __syncthreads();

    // ---- mainloop: 4 K-steps of k32, fragments via LDS.32 ----
    #pragma unroll
    for (int kk = 0; kk < 128; kk += 32) {
        uint32_t a[4][4];
        #pragma unroll
        for (int mf = 0; mf < 4; mf++) {
            const uint8_t* base = &As[(wm * 64 + mf * 16 + g) * SROW + kk + tq * 4];
            a[mf][0] = *reinterpret_cast<const uint32_t*>(base);
            a[mf][1] = *reinterpret_cast<const uint32_t*>(base + 8 * SROW);
            a[mf][2] = *reinterpret_cast<const uint32_t*>(base + 16);
            a[mf][3] = *reinterpret_cast<const uint32_t*>(base + 8 * SROW + 16);
        }
        uint32_t b[4][2];
        #pragma unroll
        for (int nf = 0; nf < 4; nf++) {
            const uint8_t* base = &Bs[(wn * 32 + nf * 8 + g) * SROW + kk + tq * 4];
            b[nf][0] = *reinterpret_cast<const uint32_t*>(base);
            b[nf][1] = *reinterpret_cast<const uint32_t*>(base + 16);
        }
        #pragma unroll
        for (int mf = 0; mf < 4; mf++)
            #pragma unroll
            for (int nf = 0; nf < 4; nf++)
                mma_e4m3(c[mf][nf], a[mf], b[nf]);
    }

    // ---- epilogue: exp(2*sim) = exp(c/128); rows always, cols if offdiag.
    // frag (mf,nf,e): row = wm*64+mf*16+g+(e>=2)*8, col = wn*32+nf*8+tq*2+(e&1)
    const float SCL = 1.0f / 128.0f;
    float csA[4], csB[4];
    #pragma unroll
    for (int nf = 0; nf < 4; nf++) { csA[nf] = 0.0f; csB[nf] = 0.0f; }

    #pragma unroll
    for (int mf = 0; mf < 4; mf++) {
        float rs0 = 0.0f, rs1 = 0.0f;
        #pragma unroll
        for (int nf = 0; nf < 4; nf++) {
            float e0 = __expf(SCL * c[mf][nf][0]);
            float e1 = __expf(SCL * c[mf][nf][1]);
            float e2 = __expf(SCL * c[mf][nf][2]);
            float e3 = __expf(SCL * c[mf][nf][3]);
            rs0 += e0 + e1;
            rs1 += e2 + e3;
            csA[nf] += e0 + e2;
            csB[nf] += e1 + e3;
        }
        #pragma unroll
        for (int o = 1; o < 4; o <<= 1) {
            rs0 += __shfl_xor_sync(0xffffffffu, rs0, o);
            rs1 += __shfl_xor_sync(0xffffffffu, rs1, o);
        }
        if (tq == 0) {
            atomicAdd(&rowsum[wm * 64 + mf * 16 + g], rs0);
            atomicAdd(&rowsum[wm * 64 + mf * 16 + g + 8], rs1);
        }
    }

    if (offdiag) {
        #pragma unroll
        for (int nf = 0; nf < 4; nf++) {
            float a = csA[nf], b = csB[nf];
            #pragma unroll
            for (int o = 4; o < 32; o <<= 1) {
                a += __shfl_xor_sync(0xffffffffu, a, o);
                b += __shfl_xor_sync(0xffffffffu, b, o);
            }
            if (lane < 4) {
                atomicAdd(&colsum[wn * 32 + nf * 8 + lane * 2], a);
                atomicAdd(&colsum[wn * 32 + nf * 8 + lane * 2 + 1], b);
            }
        }
    }
    __syncthreads();
    if (tid < 128) atomicAdd(&g_S[bi * 128 + tid], rowsum[tid]);
    if (offdiag && tid < 128) atomicAdd(&g_S[bj * 128 + tid], colsum[tid]);
}

// ------------- kernel 4: finalize (parallel) ------------------------------
__global__ void k_final(float* __restrict__ out) {
    __shared__ float red[256];
    int tid = threadIdx.x;
    int i = blockIdx.x * 256 + tid;
    float p = g_pos[i];
    float d = g_diag[i];
    float S = g_S[i];
    float denom = S - __expf(2.0f * d) + __expf(2.0f * p);
    red[tid] = -2.0f * p + logf(denom);
    __syncthreads();
    #pragma unroll
    for (int s = 128; s > 0; s >>= 1) {
        if (tid < s) red[tid] += red[tid + s];
        __syncthreads();
    }
    if (tid == 0) atomicAdd(out, red[0] / (float)NROWS);
}

extern "C" void kernel_launch(void* const* d_in, const int* in_sizes, int n_in,
                              void* d_out, int out_size) {
    const float* zi = (const float*)d_in[0];
    const float* zj = (const float*)d_in[1];
    float* out = (float*)d_out;
    (void)in_sizes; (void)n_in; (void)out_size;

    k_normalize<<<NROWS / 8, 256>>>(zi, zj);
    k_pairs<<<NROWS / 8, 256>>>(out);     // zeroes out[0], g_S
    k_simexp<<<2080, 256>>>();            // 64*65/2 lower-tri tiles
    k_final<<<32, 256>>>(out);
}

// round 11
// speedup vs baseline: 2.9396x; 1.8095x over previous
#include <cuda_runtime.h>
#include <cuda_bf16.h>
#include <cuda_fp16.h>
#include <cuda_fp8.h>
#include <cstdint>

// NT-Xent loss. loss_i = -2*p_i + log(S_i - exp(2*d_i) + exp(2*p_i)),
// S_i = sum_j exp(2*sim[i,j]), sim = R R^T (symmetric -> lower triangle only).
// Round 10: FP8 e4m3 MMA with f16 accumulators + packed ex2.approx.f16x2
// epilogue. (tcgen05 unavailable: harness PTX target is sm_103 w/o 'a'.)

#define NROWS 8192
#define HALF_N 4096
#define DIM 128

__device__ __align__(16) __nv_bfloat16 g_R[NROWS * DIM];
__device__ __align__(16) uint8_t g_R8[NROWS * DIM];   // e4m3, rows scaled by 16
__device__ float g_S[NROWS];
__device__ float g_pos[NROWS];
__device__ float g_diag[NROWS];

// ---------------- kernel 1: L2 normalize rows, write bf16 + fp8 ----------
__global__ void k_normalize(const float* __restrict__ zi, const float* __restrict__ zj) {
    int warp = (blockIdx.x * blockDim.x + threadIdx.x) >> 5;
    int lane = threadIdx.x & 31;
    if (warp >= NROWS) return;
    const float* src = (warp < HALF_N) ? (zi + (size_t)warp * DIM)
                                       : (zj + (size_t)(warp - HALF_N) * DIM);
    float4 v = reinterpret_cast<const float4*>(src)[lane];
    float ss = v.x * v.x + v.y * v.y + v.z * v.z + v.w * v.w;
    #pragma unroll
    for (int o = 16; o; o >>= 1) ss += __shfl_xor_sync(0xffffffffu, ss, o);
    float inv = 1.0f / fmaxf(sqrtf(ss), 1e-12f);
    float x = v.x * inv, y = v.y * inv, z = v.z * inv, w = v.w * inv;

    __nv_bfloat162 p0 = __nv_bfloat162(__float2bfloat16(x), __float2bfloat16(y));
    __nv_bfloat162 p1 = __nv_bfloat162(__float2bfloat16(z), __float2bfloat16(w));
    uint2 packed;
    packed.x = *reinterpret_cast<uint32_t*>(&p0);
    packed.y = *reinterpret_cast<uint32_t*>(&p1);
    reinterpret_cast<uint2*>(g_R + (size_t)warp * DIM)[lane] = packed;

    // fp8: scale by 16 (power of 2; |elem|<=1 -> <=16 < 448 max e4m3)
    uint32_t q = (uint32_t)__nv_cvt_float_to_fp8(x * 16.0f, __NV_SATFINITE, __NV_E4M3)
               | ((uint32_t)__nv_cvt_float_to_fp8(y * 16.0f, __NV_SATFINITE, __NV_E4M3) << 8)
               | ((uint32_t)__nv_cvt_float_to_fp8(z * 16.0f, __NV_SATFINITE, __NV_E4M3) << 16)
               | ((uint32_t)__nv_cvt_float_to_fp8(w * 16.0f, __NV_SATFINITE, __NV_E4M3) << 24);
    reinterpret_cast<uint32_t*>(g_R8 + (size_t)warp * DIM)[lane] = q;
}

// ------------- kernel 2: positives, diagonal, zero S, zero out ----------
__global__ void k_pairs(float* __restrict__ out) {
    int warp = (blockIdx.x * blockDim.x + threadIdx.x) >> 5;
    int lane = threadIdx.x & 31;
    if (blockIdx.x == 0 && threadIdx.x == 0) out[0] = 0.0f;
    if (warp >= NROWS) return;
    int j = warp ^ HALF_N;
    uint2 va = reinterpret_cast<const uint2*>(g_R + (size_t)warp * DIM)[lane];
    uint2 vb = reinterpret_cast<const uint2*>(g_R + (size_t)j * DIM)[lane];
    __nv_bfloat162 a0 = *reinterpret_cast<__nv_bfloat162*>(&va.x);
    __nv_bfloat162 a1 = *reinterpret_cast<__nv_bfloat162*>(&va.y);
    __nv_bfloat162 b0 = *reinterpret_cast<__nv_bfloat162*>(&vb.x);
    __nv_bfloat162 b1 = *reinterpret_cast<__nv_bfloat162*>(&vb.y);
    float ax = __bfloat162float(a0.x), ay = __bfloat162float(a0.y);
    float az = __bfloat162float(a1.x), aw = __bfloat162float(a1.y);
    float bx = __bfloat162float(b0.x), by = __bfloat162float(b0.y);
    float bz = __bfloat162float(b1.x), bw = __bfloat162float(b1.y);
    float p = ax * bx + ay * by + az * bz + aw * bw;
    float d = ax * ax + ay * ay + az * az + aw * aw;
    #pragma unroll
    for (int o = 16; o; o >>= 1) {
        p += __shfl_xor_sync(0xffffffffu, p, o);
        d += __shfl_xor_sync(0xffffffffu, d, o);
    }
    if (lane == 0) {
        g_pos[warp] = p;
        g_diag[warp] = d;
        g_S[warp] = 0.0f;
    }
}

// ------------- kernel 3: lower-triangle FP8 MMA (f16 acc) + exp sums ----
// Tile 128x128, K=128. Smem: 144B row stride -> LDS.32 fetches conflict-free.
#define SROW 144

__device__ __forceinline__ void mma_e4m3_f16(uint32_t* c, const uint32_t* a, const uint32_t* b) {
    asm volatile(
        "mma.sync.aligned.m16n8k32.row.col.f16.e4m3.e4m3.f16 "
        "{%0,%1}, {%2,%3,%4,%5}, {%6,%7}, {%0,%1};"
        : "+r"(c[0]), "+r"(c[1])
        : "r"(a[0]), "r"(a[1]), "r"(a[2]), "r"(a[3]), "r"(b[0]), "r"(b[1]));
}
__device__ __forceinline__ __half2 h2_ex2(__half2 x) {
    uint32_t r, xi = *reinterpret_cast<uint32_t*>(&x);
    asm("ex2.approx.f16x2 %0, %1;" : "=r"(r) : "r"(xi));
    return *reinterpret_cast<__half2*>(&r);
}

__global__ void __launch_bounds__(256) k_simexp() {
    __shared__ uint8_t As[128 * SROW];
    __shared__ uint8_t Bs[128 * SROW];
    __shared__ float rowsum[128];
    __shared__ float colsum[128];

    int tid = threadIdx.x;
    int wid = tid >> 5, lane = tid & 31;
    int wm = wid >> 2, wn = wid & 3;      // 2x4 warp grid; warp tile 64x32
    int g = lane >> 2, tq = lane & 3;     // group / thread-in-group

    // linear block -> lower triangle (bi, bj), bj <= bi
    int t = blockIdx.x;
    int bi = (int)((sqrtf(8.0f * (float)t + 1.0f) - 1.0f) * 0.5f);
    while ((bi + 1) * (bi + 2) / 2 <= t) bi++;
    while (bi * (bi + 1) / 2 > t) bi--;
    int bj = t - bi * (bi + 1) / 2;
    bool offdiag = (bi != bj);

    uint32_t c[4][4][2];  // f16x2 accumulators
    #pragma unroll
    for (int mf = 0; mf < 4; mf++)
        #pragma unroll
        for (int nf = 0; nf < 4; nf++) { c[mf][nf][0] = 0u; c[mf][nf][1] = 0u; }

    if (tid < 128) { rowsum[tid] = 0.0f; colsum[tid] = 0.0f; }

    // ---- load tiles: 128 rows x 128 B each = 1024 uint4 per tile ----
    {
        const uint4* gA = reinterpret_cast<const uint4*>(g_R8 + (size_t)(bi * 128) * DIM);
        const uint4* gB = reinterpret_cast<const uint4*>(g_R8 + (size_t)(bj * 128) * DIM);
        #pragma unroll
        for (int it = 0; it < 4; it++) {
            int idx = tid + 256 * it;
            int r = idx >> 3, c8 = idx & 7;
            *reinterpret_cast<uint4*>(&As[r * SROW + c8 * 16]) = gA[idx];
            *reinterpret_cast<uint4*>(&Bs[r * SROW + c8 * 16]) = gB[idx];
        }
    }
    __syncthreads();

    // ---- mainloop: 4 K-steps of k32, fragments via LDS.32 ----
    #pragma unroll
    for (int kk = 0; kk < 128; kk += 32) {
        uint32_t a[4][4];
        #pragma unroll
        for (int mf = 0; mf < 4; mf++) {
            const uint8_t* base = &As[(wm * 64 + mf * 16 + g) * SROW + kk + tq * 4];
            a[mf][0] = *reinterpret_cast<const uint32_t*>(base);
            a[mf][1] = *reinterpret_cast<const uint32_t*>(base + 8 * SROW);
            a[mf][2] = *reinterpret_cast<const uint32_t*>(base + 16);
            a[mf][3] = *reinterpret_cast<const uint32_t*>(base + 8 * SROW + 16);
        }
        uint32_t b[4][2];
        #pragma unroll
        for (int nf = 0; nf < 4; nf++) {
            const uint8_t* base = &Bs[(wn * 32 + nf * 8 + g) * SROW + kk + tq * 4];
            b[nf][0] = *reinterpret_cast<const uint32_t*>(base);
            b[nf][1] = *reinterpret_cast<const uint32_t*>(base + 16);
        }
        #pragma unroll
        for (int mf = 0; mf < 4; mf++)
            #pragma unroll
            for (int nf = 0; nf < 4; nf++)
                mma_e4m3_f16(c[mf][nf], a[mf], b[nf]);
    }

    // ---- epilogue: exp(2*sim) = 2^(c * log2e/128) via ex2.f16x2.
    // frag (mf,nf): h0 = {row r0, cols c0,c0+1}, h1 = {row r0+8, cols c0,c0+1}
    //   r0 = wm*64+mf*16+g, c0 = wn*32+nf*8+tq*2
    const __half2 SC2 = __float2half2_rn(0.01127197452f);  // log2(e)/128
    __half2 cs2[4];  // per nf: packed (col c0, col c0+1) sums over this thread's rows
    #pragma unroll
    for (int nf = 0; nf < 4; nf++) cs2[nf] = __half2half2(__ushort_as_half(0));

    #pragma unroll
    for (int mf = 0; mf < 4; mf++) {
        __half2 r0h = __half2half2(__ushort_as_half(0));
        __half2 r1h = __half2half2(__ushort_as_half(0));
        #pragma unroll
        for (int nf = 0; nf < 4; nf++) {
            __half2 h0 = *reinterpret_cast<__half2*>(&c[mf][nf][0]);
            __half2 h1 = *reinterpret_cast<__half2*>(&c[mf][nf][1]);
            __half2 e0 = h2_ex2(__hmul2(h0, SC2));   // row r0, cols c0,c0+1
            __half2 e1 = h2_ex2(__hmul2(h1, SC2));   // row r0+8
            r0h = __hadd2(r0h, e0);
            r1h = __hadd2(r1h, e1);
            cs2[nf] = __hadd2(cs2[nf], __hadd2(e0, e1));
        }
        float2 f0 = __half22float2(r0h);
        float2 f1 = __half22float2(r1h);
        float rs0 = f0.x + f0.y;
        float rs1 = f1.x + f1.y;
        #pragma unroll
        for (int o = 1; o < 4; o <<= 1) {
            rs0 += __shfl_xor_sync(0xffffffffu, rs0, o);
            rs1 += __shfl_xor_sync(0xffffffffu, rs1, o);
        }
        if (tq == 0) {
            atomicAdd(&rowsum[wm * 64 + mf * 16 + g], rs0);
            atomicAdd(&rowsum[wm * 64 + mf * 16 + g + 8], rs1);
        }
    }

    if (offdiag) {
        #pragma unroll
        for (int nf = 0; nf < 4; nf++) {
            float2 f = __half22float2(cs2[nf]);
            float a = f.x, b = f.y;
            #pragma unroll
            for (int o = 4; o < 32; o <<= 1) {
                a += __shfl_xor_sync(0xffffffffu, a, o);
                b += __shfl_xor_sync(0xffffffffu, b, o);
            }
            if (lane < 4) {
                atomicAdd(&colsum[wn * 32 + nf * 8 + lane * 2], a);
                atomicAdd(&colsum[wn * 32 + nf * 8 + lane * 2 + 1], b);
            }
        }
    }
    __syncthreads();
    if (tid < 128) atomicAdd(&g_S[bi * 128 + tid], rowsum[tid]);
    if (offdiag && tid < 128) atomicAdd(&g_S[bj * 128 + tid], colsum[tid]);
}

// ------------- kernel 4: finalize (parallel) ------------------------------
__global__ void k_final(float* __restrict__ out) {
    __shared__ float red[256];
    int tid = threadIdx.x;
    int i = blockIdx.x * 256 + tid;
    float p = g_pos[i];
    float d = g_diag[i];
    float S = g_S[i];
    float denom = S - __expf(2.0f * d) + __expf(2.0f * p);
    red[tid] = -2.0f * p + logf(denom);
    __syncthreads();
    #pragma unroll
    for (int s = 128; s > 0; s >>= 1) {
        if (tid < s) red[tid] += red[tid + s];
        __syncthreads();
    }
    if (tid == 0) atomicAdd(out, red[0] / (float)NROWS);
}

extern "C" void kernel_launch(void* const* d_in, const int* in_sizes, int n_in,
                              void* d_out, int out_size) {
    const float* zi = (const float*)d_in[0];
    const float* zj = (const float*)d_in[1];
    float* out = (float*)d_out;
    (void)in_sizes; (void)n_in; (void)out_size;

    k_normalize<<<NROWS / 8, 256>>>(zi, zj);
    k_pairs<<<NROWS / 8, 256>>>(out);     // zeroes out[0], g_S
    k_simexp<<<2080, 256>>>();            // 64*65/2 lower-tri tiles
    k_final<<<32, 256>>>(out);
}

// round 12
// speedup vs baseline: 2.9623x; 1.0077x over previous
#include <cuda_runtime.h>
#include <cuda_bf16.h>
#include <cuda_fp16.h>
#include <cuda_fp8.h>
#include <cstdint>

// NT-Xent loss. loss_i = -2*p_i + log(S_i - exp(2*d_i) + exp(2*p_i)),
// S_i = sum_j exp(2*sim[i,j]), sim = R R^T (symmetric -> lower triangle only).
// Round 12: fused normalize+pairs front-end (fp32 positives, fp8-exact diag);
// k_simexp fragment fetch via ldmatrix.x4. FP8 e4m3 MMA, f16 accum,
// packed ex2.f16x2 epilogue. (tcgen05 unavailable: PTX target sm_103 w/o 'a'.)

#define NROWS 8192
#define HALF_N 4096
#define DIM 128

__device__ __align__(16) uint8_t g_R8[NROWS * DIM];   // e4m3, rows scaled by 16
__device__ float g_S[NROWS];
__device__ float g_pos[NROWS];
__device__ float g_diag[NROWS];   // diag of fp8 sim: ||q||^2 / 256

// ---- kernel 1: fused L2-normalize (both views) + pos/diag + init --------
// warp w owns pair (i = w, j = w + HALF_N).
__global__ void k_fused(const float* __restrict__ zi, const float* __restrict__ zj,
                        float* __restrict__ out) {
    int warp = (blockIdx.x * blockDim.x + threadIdx.x) >> 5;
    int lane = threadIdx.x & 31;
    if (blockIdx.x == 0 && threadIdx.x == 0) out[0] = 0.0f;
    if (warp >= HALF_N) return;
    int i = warp, j = warp + HALF_N;

    float4 vi = reinterpret_cast<const float4*>(zi + (size_t)i * DIM)[lane];
    float4 vj = reinterpret_cast<const float4*>(zj + (size_t)i * DIM)[lane];
    float si = vi.x * vi.x + vi.y * vi.y + vi.z * vi.z + vi.w * vi.w;
    float sj = vj.x * vj.x + vj.y * vj.y + vj.z * vj.z + vj.w * vj.w;
    #pragma unroll
    for (int o = 16; o; o >>= 1) {
        si += __shfl_xor_sync(0xffffffffu, si, o);
        sj += __shfl_xor_sync(0xffffffffu, sj, o);
    }
    float inv_i = 1.0f / fmaxf(sqrtf(si), 1e-12f);
    float inv_j = 1.0f / fmaxf(sqrtf(sj), 1e-12f);
    float ax = vi.x * inv_i, ay = vi.y * inv_i, az = vi.z * inv_i, aw = vi.w * inv_i;
    float bx = vj.x * inv_j, by = vj.y * inv_j, bz = vj.z * inv_j, bw = vj.w * inv_j;

    // positive similarity from fp32 normalized values (matches reference best)
    float p = ax * bx + ay * by + az * bz + aw * bw;

    // fp8 quantize (scale 16; power of 2, |elem|<=16 < 448)
    uint32_t qi = (uint32_t)__nv_cvt_float_to_fp8(ax * 16.0f, __NV_SATFINITE, __NV_E4M3)
                | ((uint32_t)__nv_cvt_float_to_fp8(ay * 16.0f, __NV_SATFINITE, __NV_E4M3) << 8)
                | ((uint32_t)__nv_cvt_float_to_fp8(az * 16.0f, __NV_SATFINITE, __NV_E4M3) << 16)
                | ((uint32_t)__nv_cvt_float_to_fp8(aw * 16.0f, __NV_SATFINITE, __NV_E4M3) << 24);
    uint32_t qj = (uint32_t)__nv_cvt_float_to_fp8(bx * 16.0f, __NV_SATFINITE, __NV_E4M3)
                | ((uint32_t)__nv_cvt_float_to_fp8(by * 16.0f, __NV_SATFINITE, __NV_E4M3) << 8)
                | ((uint32_t)__nv_cvt_float_to_fp8(bz * 16.0f, __NV_SATFINITE, __NV_E4M3) << 16)
                | ((uint32_t)__nv_cvt_float_to_fp8(bw * 16.0f, __NV_SATFINITE, __NV_E4M3) << 24);
    reinterpret_cast<uint32_t*>(g_R8 + (size_t)i * DIM)[lane] = qi;
    reinterpret_cast<uint32_t*>(g_R8 + (size_t)j * DIM)[lane] = qj;

    // diag of the fp8 similarity (exact cancellation vs GEMM's diagonal term)
    __half2_raw hi0 = __nv_cvt_fp8x2_to_halfraw2((__nv_fp8x2_storage_t)(qi & 0xFFFF), __NV_E4M3);
    __half2_raw hi1 = __nv_cvt_fp8x2_to_halfraw2((__nv_fp8x2_storage_t)(qi >> 16), __NV_E4M3);
    __half2_raw hj0 = __nv_cvt_fp8x2_to_halfraw2((__nv_fp8x2_storage_t)(qj & 0xFFFF), __NV_E4M3);
    __half2_raw hj1 = __nv_cvt_fp8x2_to_halfraw2((__nv_fp8x2_storage_t)(qj >> 16), __NV_E4M3);
    float2 fi0 = __half22float2(*reinterpret_cast<__half2*>(&hi0));
    float2 fi1 = __half22float2(*reinterpret_cast<__half2*>(&hi1));
    float2 fj0 = __half22float2(*reinterpret_cast<__half2*>(&hj0));
    float2 fj1 = __half22float2(*reinterpret_cast<__half2*>(&hj1));
    float di = fi0.x * fi0.x + fi0.y * fi0.y + fi1.x * fi1.x + fi1.y * fi1.y;
    float dj = fj0.x * fj0.x + fj0.y * fj0.y + fj1.x * fj1.x + fj1.y * fj1.y;

    #pragma unroll
    for (int o = 16; o; o >>= 1) {
        p  += __shfl_xor_sync(0xffffffffu, p, o);
        di += __shfl_xor_sync(0xffffffffu, di, o);
        dj += __shfl_xor_sync(0xffffffffu, dj, o);
    }
    if (lane == 0) {
        g_pos[i] = p;  g_pos[j] = p;
        g_diag[i] = di * (1.0f / 256.0f);
        g_diag[j] = dj * (1.0f / 256.0f);
        g_S[i] = 0.0f; g_S[j] = 0.0f;
    }
}

// ------------- kernel 2: lower-triangle FP8 MMA (f16 acc) + exp sums ----
// Tile 128x128, K=128. 144B row stride: LDSM 8-row phases are bank-perfect.
#define SROW 144

__device__ __forceinline__ void mma_e4m3_f16(uint32_t* c, const uint32_t* a, const uint32_t* b) {
    asm volatile(
        "mma.sync.aligned.m16n8k32.row.col.f16.e4m3.e4m3.f16 "
        "{%0,%1}, {%2,%3,%4,%5}, {%6,%7}, {%0,%1};"
        : "+r"(c[0]), "+r"(c[1])
        : "r"(a[0]), "r"(a[1]), "r"(a[2]), "r"(a[3]), "r"(b[0]), "r"(b[1]));
}
__device__ __forceinline__ void ldsm_x4(uint32_t* r, uint32_t addr) {
    asm volatile("ldmatrix.sync.aligned.m8n8.x4.shared.b16 {%0,%1,%2,%3}, [%4];"
                 : "=r"(r[0]), "=r"(r[1]), "=r"(r[2]), "=r"(r[3]) : "r"(addr));
}
__device__ __forceinline__ __half2 h2_ex2(__half2 x) {
    uint32_t r, xi = *reinterpret_cast<uint32_t*>(&x);
    asm("ex2.approx.f16x2 %0, %1;" : "=r"(r) : "r"(xi));
    return *reinterpret_cast<__half2*>(&r);
}

__global__ void __launch_bounds__(256) k_simexp() {
    __shared__ uint8_t As[128 * SROW];
    __shared__ uint8_t Bs[128 * SROW];
    __shared__ float rowsum[128];
    __shared__ float colsum[128];

    int tid = threadIdx.x;
    int wid = tid >> 5, lane = tid & 31;
    int wm = wid >> 2, wn = wid & 3;      // 2x4 warp grid; warp tile 64x32
    int g = lane >> 2, tq = lane & 3;

    // linear block -> lower triangle (bi, bj), bj <= bi
    int t = blockIdx.x;
    int bi = (int)((sqrtf(8.0f * (float)t + 1.0f) - 1.0f) * 0.5f);
    while ((bi + 1) * (bi + 2) / 2 <= t) bi++;
    while (bi * (bi + 1) / 2 > t) bi--;
    int bj = t - bi * (bi + 1) / 2;
    bool offdiag = (bi != bj);

    uint32_t c[4][4][2];  // f16x2 accumulators
    #pragma unroll
    for (int mf = 0; mf < 4; mf++)
        #pragma unroll
        for (int nf = 0; nf < 4; nf++) { c[mf][nf][0] = 0u; c[mf][nf][1] = 0u; }

    if (tid < 128) { rowsum[tid] = 0.0f; colsum[tid] = 0.0f; }

    // ---- load tiles: 128 rows x 128 B each = 1024 uint4 per tile ----
    {
        const uint4* gA = reinterpret_cast<const uint4*>(g_R8 + (size_t)(bi * 128) * DIM);
        const uint4* gB = reinterpret_cast<const uint4*>(g_R8 + (size_t)(bj * 128) * DIM);
        #pragma unroll
        for (int it = 0; it < 4; it++) {
            int idx = tid + 256 * it;
            int r = idx >> 3, c8 = idx & 7;
            *reinterpret_cast<uint4*>(&As[r * SROW + c8 * 16]) = gA[idx];
            *reinterpret_cast<uint4*>(&Bs[r * SROW + c8 * 16]) = gB[idx];
        }
    }
    __syncthreads();

    // ---- mainloop: 4 K-steps of k32; fragments via ldmatrix.x4 ----
    // A x4 (per mf): matrices {rows 0-7,kk},{rows 8-15,kk},{rows 0-7,kk+16},{rows 8-15,kk+16}
    uint32_t aBase = (uint32_t)__cvta_generic_to_shared(As) +
                     (uint32_t)((wm * 64 + ((lane >> 3) & 1) * 8 + (lane & 7)) * SROW +
                                ((lane >> 4) & 1) * 16);
    // B x4 (per nf-pair): {rows nfp*16+0-7,kk},{same,kk+16},{rows +8-15,kk},{same,kk+16}
    uint32_t bBase = (uint32_t)__cvta_generic_to_shared(Bs) +
                     (uint32_t)((wn * 32 + ((lane >> 4) & 1) * 8 + (lane & 7)) * SROW +
                                ((lane >> 3) & 1) * 16);

    #pragma unroll
    for (int kk = 0; kk < 128; kk += 32) {
        uint32_t a[4][4];
        #pragma unroll
        for (int mf = 0; mf < 4; mf++)
            ldsm_x4(a[mf], aBase + (uint32_t)(mf * 16 * SROW + kk));
        uint32_t b[4][2];
        #pragma unroll
        for (int nfp = 0; nfp < 2; nfp++) {
            uint32_t r[4];
            ldsm_x4(r, bBase + (uint32_t)(nfp * 16 * SROW + kk));
            b[2 * nfp][0] = r[0]; b[2 * nfp][1] = r[1];
            b[2 * nfp + 1][0] = r[2]; b[2 * nfp + 1][1] = r[3];
        }
        #pragma unroll
        for (int mf = 0; mf < 4; mf++)
            #pragma unroll
            for (int nf = 0; nf < 4; nf++)
                mma_e4m3_f16(c[mf][nf], a[mf], b[nf]);
    }

    // ---- epilogue: exp(2*sim) = 2^(c * log2e/128) via ex2.f16x2.
    // frag (mf,nf): h0 = {row r0, cols c0,c0+1}, h1 = {row r0+8, same cols}
    //   r0 = wm*64+mf*16+g, c0 = wn*32+nf*8+tq*2
    const __half2 SC2 = __float2half2_rn(0.01127197452f);  // log2(e)/128
    __half2 cs2[4];
    #pragma unroll
    for (int nf = 0; nf < 4; nf++) cs2[nf] = __half2half2(__ushort_as_half(0));

    #pragma unroll
    for (int mf = 0; mf < 4; mf++) {
        __half2 r0h = __half2half2(__ushort_as_half(0));
        __half2 r1h = __half2half2(__ushort_as_half(0));
        #pragma unroll
        for (int nf = 0; nf < 4; nf++) {
            __half2 h0 = *reinterpret_cast<__half2*>(&c[mf][nf][0]);
            __half2 h1 = *reinterpret_cast<__half2*>(&c[mf][nf][1]);
            __half2 e0 = h2_ex2(__hmul2(h0, SC2));
            __half2 e1 = h2_ex2(__hmul2(h1, SC2));
            r0h = __hadd2(r0h, e0);
            r1h = __hadd2(r1h, e1);
            cs2[nf] = __hadd2(cs2[nf], __hadd2(e0, e1));
        }
        float2 f0 = __half22float2(r0h);
        float2 f1 = __half22float2(r1h);
        float rs0 = f0.x + f0.y;
        float rs1 = f1.x + f1.y;
        #pragma unroll
        for (int o = 1; o < 4; o <<= 1) {
            rs0 += __shfl_xor_sync(0xffffffffu, rs0, o);
            rs1 += __shfl_xor_sync(0xffffffffu, rs1, o);
        }
        if (tq == 0) {
            atomicAdd(&rowsum[wm * 64 + mf * 16 + g], rs0);
            atomicAdd(&rowsum[wm * 64 + mf * 16 + g + 8], rs1);
        }
    }

    if (offdiag) {
        #pragma unroll
        for (int nf = 0; nf < 4; nf++) {
            float2 f = __half22float2(cs2[nf]);
            float a = f.x, b = f.y;
            #pragma unroll
            for (int o = 4; o < 32; o <<= 1) {
                a += __shfl_xor_sync(0xffffffffu, a, o);
                b += __shfl_xor_sync(0xffffffffu, b, o);
            }
            if (lane < 4) {
                atomicAdd(&colsum[wn * 32 + nf * 8 + lane * 2], a);
                atomicAdd(&colsum[wn * 32 + nf * 8 + lane * 2 + 1], b);
            }
        }
    }
    __syncthreads();
    if (tid < 128) atomicAdd(&g_S[bi * 128 + tid], rowsum[tid]);
    if (offdiag && tid < 128) atomicAdd(&g_S[bj * 128 + tid], colsum[tid]);
}

// ------------- kernel 3: finalize (parallel) ------------------------------
__global__ void k_final(float* __restrict__ out) {
    __shared__ float red[256];
    int tid = threadIdx.x;
    int i = blockIdx.x * 256 + tid;
    float p = g_pos[i];
    float d = g_diag[i];
    float S = g_S[i];
    float denom = S - __expf(2.0f * d) + __expf(2.0f * p);
    red[tid] = -2.0f * p + logf(denom);
    __syncthreads();
    #pragma unroll
    for (int s = 128; s > 0; s >>= 1) {
        if (tid < s) red[tid] += red[tid + s];
        __syncthreads();
    }
    if (tid == 0) atomicAdd(out, red[0] / (float)NROWS);
}

extern "C" void kernel_launch(void* const* d_in, const int* in_sizes, int n_in,
                              void* d_out, int out_size) {
    const float* zi = (const float*)d_in[0];
    const float* zj = (const float*)d_in[1];
    float* out = (float*)d_out;
    (void)in_sizes; (void)n_in; (void)out_size;

    k_fused<<<HALF_N / 8, 256>>>(zi, zj, out);  // normalize+quantize+pos/diag, init
    k_simexp<<<2080, 256>>>();                  // 64*65/2 lower-tri tiles
    k_final<<<32, 256>>>(out);
}

// round 15
// speedup vs baseline: 2.9853x; 1.0078x over previous
#include <cuda_runtime.h>
#include <cuda_bf16.h>
#include <cuda_fp16.h>
#include <cuda_fp8.h>
#include <cstdint>

// NT-Xent loss. loss_i = -2*p_i + log(S_i - exp(2*d_i) + exp(2*p_i)),
// S_i = sum_j exp(2*sim[i,j]), sim = R R^T (symmetric -> lower triangle only).
// Round 15 (resubmit of round 13; infra failure, kernel never ran):
// occupancy push (3 CTAs/SM via launch_bounds + cp.async loads),
// faster k_final/k_fused tails. FP8 e4m3 MMA, f16 accum, ex2.f16x2 epilogue.

#define NROWS 8192
#define HALF_N 4096
#define DIM 128

__device__ __align__(16) uint8_t g_R8[NROWS * DIM];   // e4m3, rows scaled by 16
__device__ float g_S[NROWS];
__device__ float g_pos[NROWS];
__device__ float g_diag[NROWS];   // diag of fp8 sim: ||q||^2 / 256

// ---- kernel 1: fused L2-normalize (both views) + pos/diag + init --------
__global__ void __launch_bounds__(128) k_fused(const float* __restrict__ zi,
                                               const float* __restrict__ zj,
                                               float* __restrict__ out) {
    int warp = (blockIdx.x * blockDim.x + threadIdx.x) >> 5;
    int lane = threadIdx.x & 31;
    if (blockIdx.x == 0 && threadIdx.x == 0) out[0] = 0.0f;
    if (warp >= HALF_N) return;
    int i = warp, j = warp + HALF_N;

    float4 vi = reinterpret_cast<const float4*>(zi + (size_t)i * DIM)[lane];
    float4 vj = reinterpret_cast<const float4*>(zj + (size_t)i * DIM)[lane];
    float si = vi.x * vi.x + vi.y * vi.y + vi.z * vi.z + vi.w * vi.w;
    float sj = vj.x * vj.x + vj.y * vj.y + vj.z * vj.z + vj.w * vj.w;
    #pragma unroll
    for (int o = 16; o; o >>= 1) {
        si += __shfl_xor_sync(0xffffffffu, si, o);
        sj += __shfl_xor_sync(0xffffffffu, sj, o);
    }
    float inv_i = rsqrtf(fmaxf(si, 1e-24f));
    float inv_j = rsqrtf(fmaxf(sj, 1e-24f));
    float ax = vi.x * inv_i, ay = vi.y * inv_i, az = vi.z * inv_i, aw = vi.w * inv_i;
    float bx = vj.x * inv_j, by = vj.y * inv_j, bz = vj.z * inv_j, bw = vj.w * inv_j;

    float p = ax * bx + ay * by + az * bz + aw * bw;  // fp32 positive

    uint32_t qi = (uint32_t)__nv_cvt_float_to_fp8(ax * 16.0f, __NV_SATFINITE, __NV_E4M3)
                | ((uint32_t)__nv_cvt_float_to_fp8(ay * 16.0f, __NV_SATFINITE, __NV_E4M3) << 8)
                | ((uint32_t)__nv_cvt_float_to_fp8(az * 16.0f, __NV_SATFINITE, __NV_E4M3) << 16)
                | ((uint32_t)__nv_cvt_float_to_fp8(aw * 16.0f, __NV_SATFINITE, __NV_E4M3) << 24);
    uint32_t qj = (uint32_t)__nv_cvt_float_to_fp8(bx * 16.0f, __NV_SATFINITE, __NV_E4M3)
                | ((uint32_t)__nv_cvt_float_to_fp8(by * 16.0f, __NV_SATFINITE, __NV_E4M3) << 8)
                | ((uint32_t)__nv_cvt_float_to_fp8(bz * 16.0f, __NV_SATFINITE, __NV_E4M3) << 16)
                | ((uint32_t)__nv_cvt_float_to_fp8(bw * 16.0f, __NV_SATFINITE, __NV_E4M3) << 24);
    reinterpret_cast<uint32_t*>(g_R8 + (size_t)i * DIM)[lane] = qi;
    reinterpret_cast<uint32_t*>(g_R8 + (size_t)j * DIM)[lane] = qj;

    // diag of fp8 similarity (exact cancellation vs GEMM diagonal)
    __half2_raw hi0 = __nv_cvt_fp8x2_to_halfraw2((__nv_fp8x2_storage_t)(qi & 0xFFFF), __NV_E4M3);
    __half2_raw hi1 = __nv_cvt_fp8x2_to_halfraw2((__nv_fp8x2_storage_t)(qi >> 16), __NV_E4M3);
    __half2_raw hj0 = __nv_cvt_fp8x2_to_halfraw2((__nv_fp8x2_storage_t)(qj & 0xFFFF), __NV_E4M3);
    __half2_raw hj1 = __nv_cvt_fp8x2_to_halfraw2((__nv_fp8x2_storage_t)(qj >> 16), __NV_E4M3);
    float2 fi0 = __half22float2(*reinterpret_cast<__half2*>(&hi0));
    float2 fi1 = __half22float2(*reinterpret_cast<__half2*>(&hi1));
    float2 fj0 = __half22float2(*reinterpret_cast<__half2*>(&hj0));
    float2 fj1 = __half22float2(*reinterpret_cast<__half2*>(&hj1));
    float di = fi0.x * fi0.x + fi0.y * fi0.y + fi1.x * fi1.x + fi1.y * fi1.y;
    float dj = fj0.x * fj0.x + fj0.y * fj0.y + fj1.x * fj1.x + fj1.y * fj1.y;

    #pragma unroll
    for (int o = 16; o; o >>= 1) {
        p  += __shfl_xor_sync(0xffffffffu, p, o);
        di += __shfl_xor_sync(0xffffffffu, di, o);
        dj += __shfl_xor_sync(0xffffffffu, dj, o);
    }
    if (lane == 0) {
        g_pos[i] = p;  g_pos[j] = p;
        g_diag[i] = di * (1.0f / 256.0f);
        g_diag[j] = dj * (1.0f / 256.0f);
        g_S[i] = 0.0f; g_S[j] = 0.0f;
    }
}

// ------------- kernel 2: lower-triangle FP8 MMA (f16 acc) + exp sums ----
#define SROW 144

__device__ __forceinline__ void mma_e4m3_f16(uint32_t* c, const uint32_t* a, const uint32_t* b) {
    asm volatile(
        "mma.sync.aligned.m16n8k32.row.col.f16.e4m3.e4m3.f16 "
        "{%0,%1}, {%2,%3,%4,%5}, {%6,%7}, {%0,%1};"
        : "+r"(c[0]), "+r"(c[1])
        : "r"(a[0]), "r"(a[1]), "r"(a[2]), "r"(a[3]), "r"(b[0]), "r"(b[1]));
}
__device__ __forceinline__ void ldsm_x4(uint32_t* r, uint32_t addr) {
    asm volatile("ldmatrix.sync.aligned.m8n8.x4.shared.b16 {%0,%1,%2,%3}, [%4];"
                 : "=r"(r[0]), "=r"(r[1]), "=r"(r[2]), "=r"(r[3]) : "r"(addr));
}
__device__ __forceinline__ __half2 h2_ex2(__half2 x) {
    uint32_t r, xi = *reinterpret_cast<uint32_t*>(&x);
    asm("ex2.approx.f16x2 %0, %1;" : "=r"(r) : "r"(xi));
    return *reinterpret_cast<__half2*>(&r);
}
__device__ __forceinline__ void cp16(uint32_t dst, const void* src) {
    asm volatile("cp.async.cg.shared.global [%0], [%1], 16;" :: "r"(dst), "l"(src));
}

__global__ void __launch_bounds__(256, 3) k_simexp() {
    __shared__ uint8_t As[128 * SROW];
    __shared__ uint8_t Bs[128 * SROW];
    __shared__ float rowsum[128];
    __shared__ float colsum[128];

    int tid = threadIdx.x;
    int wid = tid >> 5, lane = tid & 31;
    int wm = wid >> 2, wn = wid & 3;      // 2x4 warp grid; warp tile 64x32
    int g = lane >> 2, tq = lane & 3;

    // linear block -> lower triangle (bi, bj), bj <= bi
    int t = blockIdx.x;
    int bi = (int)((sqrtf(8.0f * (float)t + 1.0f) - 1.0f) * 0.5f);
    while ((bi + 1) * (bi + 2) / 2 <= t) bi++;
    while (bi * (bi + 1) / 2 > t) bi--;
    int bj = t - bi * (bi + 1) / 2;
    bool offdiag = (bi != bj);

    // ---- async tile loads: 128 rows x 128 B per tile, cp.async 16B ----
    {
        uint32_t sA = (uint32_t)__cvta_generic_to_shared(As);
        uint32_t sB = (uint32_t)__cvta_generic_to_shared(Bs);
        const uint4* gA = reinterpret_cast<const uint4*>(g_R8 + (size_t)(bi * 128) * DIM);
        const uint4* gB = reinterpret_cast<const uint4*>(g_R8 + (size_t)(bj * 128) * DIM);
        #pragma unroll
        for (int it = 0; it < 4; it++) {
            int idx = tid + 256 * it;
            int r = idx >> 3, c8 = idx & 7;
            uint32_t so = (uint32_t)(r * SROW + c8 * 16);
            cp16(sA + so, gA + idx);
            cp16(sB + so, gB + idx);
        }
        asm volatile("cp.async.commit_group;" ::: "memory");
    }

    uint32_t c[4][4][2];
    #pragma unroll
    for (int mf = 0; mf < 4; mf++)
        #pragma unroll
        for (int nf = 0; nf < 4; nf++) { c[mf][nf][0] = 0u; c[mf][nf][1] = 0u; }
    if (tid < 128) { rowsum[tid] = 0.0f; colsum[tid] = 0.0f; }

    asm volatile("cp.async.wait_group 0;" ::: "memory");
    __syncthreads();

    // ---- mainloop: 4 K-steps of k32; fragments via ldmatrix.x4 ----
    uint32_t aBase = (uint32_t)__cvta_generic_to_shared(As) +
                     (uint32_t)((wm * 64 + ((lane >> 3) & 1) * 8 + (lane & 7)) * SROW +
                                ((lane >> 4) & 1) * 16);
    uint32_t bBase = (uint32_t)__cvta_generic_to_shared(Bs) +
                     (uint32_t)((wn * 32 + ((lane >> 4) & 1) * 8 + (lane & 7)) * SROW +
                                ((lane >> 3) & 1) * 16);

    #pragma unroll
    for (int kk = 0; kk < 128; kk += 32) {
        uint32_t a[4][4];
        #pragma unroll
        for (int mf = 0; mf < 4; mf++)
            ldsm_x4(a[mf], aBase + (uint32_t)(mf * 16 * SROW + kk));
        uint32_t b[4][2];
        #pragma unroll
        for (int nfp = 0; nfp < 2; nfp++) {
            uint32_t r[4];
            ldsm_x4(r, bBase + (uint32_t)(nfp * 16 * SROW + kk));
            b[2 * nfp][0] = r[0]; b[2 * nfp][1] = r[1];
            b[2 * nfp + 1][0] = r[2]; b[2 * nfp + 1][1] = r[3];
        }
        #pragma unroll
        for (int mf = 0; mf < 4; mf++)
            #pragma unroll
            for (int nf = 0; nf < 4; nf++)
                mma_e4m3_f16(c[mf][nf], a[mf], b[nf]);
    }

    // ---- epilogue: exp(2*sim) = 2^(c * log2e/128) via ex2.f16x2 ----
    const __half2 SC2 = __float2half2_rn(0.01127197452f);  // log2(e)/128
    __half2 cs2[4];
    #pragma unroll
    for (int nf = 0; nf < 4; nf++) cs2[nf] = __half2half2(__ushort_as_half(0));

    #pragma unroll
    for (int mf = 0; mf < 4; mf++) {
        __half2 r0h = __half2half2(__ushort_as_half(0));
        __half2 r1h = __half2half2(__ushort_as_half(0));
        #pragma unroll
        for (int nf = 0; nf < 4; nf++) {
            __half2 h0 = *reinterpret_cast<__half2*>(&c[mf][nf][0]);
            __half2 h1 = *reinterpret_cast<__half2*>(&c[mf][nf][1]);
            __half2 e0 = h2_ex2(__hmul2(h0, SC2));
            __half2 e1 = h2_ex2(__hmul2(h1, SC2));
            r0h = __hadd2(r0h, e0);
            r1h = __hadd2(r1h, e1);
            cs2[nf] = __hadd2(cs2[nf], __hadd2(e0, e1));
        }
        float2 f0 = __half22float2(r0h);
        float2 f1 = __half22float2(r1h);
        float rs0 = f0.x + f0.y;
        float rs1 = f1.x + f1.y;
        #pragma unroll
        for (int o = 1; o < 4; o <<= 1) {
            rs0 += __shfl_xor_sync(0xffffffffu, rs0, o);
            rs1 += __shfl_xor_sync(0xffffffffu, rs1, o);
        }
        if (tq == 0) {
            atomicAdd(&rowsum[wm * 64 + mf * 16 + g], rs0);
            atomicAdd(&rowsum[wm * 64 + mf * 16 + g + 8], rs1);
        }
    }

    if (offdiag) {
        #pragma unroll
        for (int nf = 0; nf < 4; nf++) {
            float2 f = __half22float2(cs2[nf]);
            float a = f.x, b = f.y;
            #pragma unroll
            for (int o = 4; o < 32; o <<= 1) {
                a += __shfl_xor_sync(0xffffffffu, a, o);
                b += __shfl_xor_sync(0xffffffffu, b, o);
            }
            if (lane < 4) {
                atomicAdd(&colsum[wn * 32 + nf * 8 + lane * 2], a);
                atomicAdd(&colsum[wn * 32 + nf * 8 + lane * 2 + 1], b);
            }
        }
    }
    __syncthreads();
    if (tid < 128) atomicAdd(&g_S[bi * 128 + tid], rowsum[tid]);
    if (offdiag && tid < 128) atomicAdd(&g_S[bj * 128 + tid], colsum[tid]);
}

// ------------- kernel 3: finalize (parallel, warp-shuffle reduce) --------
__global__ void __launch_bounds__(128) k_final(float* __restrict__ out) {
    __shared__ float part[4];
    int tid = threadIdx.x;
    int i = blockIdx.x * 128 + tid;  // 64 blocks x 128 = 8192 rows
    float p = g_pos[i];
    float d = g_diag[i];
    float S = g_S[i];
    float denom = S - __expf(2.0f * d) + __expf(2.0f * p);
    float v = -2.0f * p + __logf(denom);
    #pragma unroll
    for (int o = 16; o; o >>= 1) v += __shfl_xor_sync(0xffffffffu, v, o);
    if ((tid & 31) == 0) part[tid >> 5] = v;
    __syncthreads();
    if (tid == 0) {
        float s = part[0] + part[1] + part[2] + part[3];
        atomicAdd(out, s * (1.0f / (float)NROWS));
    }
}

extern "C" void kernel_launch(void* const* d_in, const int* in_sizes, int n_in,
                              void* d_out, int out_size) {
    const float* zi = (const float*)d_in[0];
    const float* zj = (const float*)d_in[1];
    float* out = (float*)d_out;
    (void)in_sizes; (void)n_in; (void)out_size;

    k_fused<<<HALF_N / 4, 128>>>(zi, zj, out);  // normalize+quantize+pos/diag, init
    k_simexp<<<2080, 256>>>();                  // 64*65/2 lower-tri tiles
    k_final<<<64, 128>>>(out);
}